// round 14
// baseline (speedup 1.0000x reference)
#include <cuda_runtime.h>
#include <cstdint>
#include <cstddef>

// Problem dims
#define NB   64
#define LQ   2048
#define INQ  128
#define HH   256
#define AQ   18
#define G3   768
#define ROWS_TOT 131072              // NB*LQ

// Output layout (floats): q [64,2048,18] | gru_out [64,2048,256] | next_hx [1,64,256]
#define Q_ELEMS    2359296ULL
#define GRU_ELEMS  33554432ULL

// ---------------------------------------------------------------------------
// Scratch (static device globals -- allocation APIs are forbidden)
// ---------------------------------------------------------------------------
__device__ float g_gi[(size_t)ROWS_TOT * G3];   // input projections [N*L, 768]
__device__ float g_m0[(size_t)ROWS_TOT * HH];   // fc0 output
__device__ float g_m1[(size_t)ROWS_TOT * HH];   // fc1 output

// ===========================================================================
// Generic tiled fp32 GEMM:  C[M,N] = act( A[M,K] @ B[N,K]^T + bias[N] )
// BM=64, BN=64, BK=16, 256 threads, 4x4 register micro-tile.
// M % 64 == 0 and K % 16 == 0 always hold here; N may be ragged (fc2: N=18).
// ===========================================================================
#define BM 64
#define BN 64
#define BKK 16

template<bool RELU_IN, bool RELU_OUT>
__global__ void __launch_bounds__(256)
gemm_bias(const float* __restrict__ A, const float* __restrict__ B,
          const float* __restrict__ bias, float* __restrict__ C,
          int M, int N, int K)
{
    __shared__ float As[BM * BKK];   // [row][k]
    __shared__ float Bs[BKK * BN];   // [k][col] (transposed on load)

    const int tid  = threadIdx.x;
    const int row0 = blockIdx.x * BM;
    const int col0 = blockIdx.y * BN;
    const int lr = tid >> 2;         // 0..63 loader row
    const int lc = tid & 3;          // 0..3  loader k-quad
    const int ty = tid >> 4;         // 0..15
    const int tx = tid & 15;         // 0..15

    float acc[4][4];
    #pragma unroll
    for (int i = 0; i < 4; i++)
        #pragma unroll
        for (int j = 0; j < 4; j++) acc[i][j] = 0.f;

    for (int k0 = 0; k0 < K; k0 += BKK) {
        float4 av = *(const float4*)(A + (size_t)(row0 + lr) * K + k0 + lc * 4);
        if (RELU_IN) {
            av.x = fmaxf(av.x, 0.f); av.y = fmaxf(av.y, 0.f);
            av.z = fmaxf(av.z, 0.f); av.w = fmaxf(av.w, 0.f);
        }
        *(float4*)(As + lr * BKK + lc * 4) = av;

        float4 bv = make_float4(0.f, 0.f, 0.f, 0.f);
        if (col0 + lr < N)
            bv = *(const float4*)(B + (size_t)(col0 + lr) * K + k0 + lc * 4);
        Bs[(lc * 4 + 0) * BN + lr] = bv.x;
        Bs[(lc * 4 + 1) * BN + lr] = bv.y;
        Bs[(lc * 4 + 2) * BN + lr] = bv.z;
        Bs[(lc * 4 + 3) * BN + lr] = bv.w;
        __syncthreads();

        #pragma unroll
        for (int k = 0; k < BKK; k++) {
            float a0 = As[(ty * 4 + 0) * BKK + k];
            float a1 = As[(ty * 4 + 1) * BKK + k];
            float a2 = As[(ty * 4 + 2) * BKK + k];
            float a3 = As[(ty * 4 + 3) * BKK + k];
            float4 b4 = *(const float4*)(Bs + k * BN + tx * 4);
            acc[0][0] = fmaf(a0, b4.x, acc[0][0]); acc[0][1] = fmaf(a0, b4.y, acc[0][1]);
            acc[0][2] = fmaf(a0, b4.z, acc[0][2]); acc[0][3] = fmaf(a0, b4.w, acc[0][3]);
            acc[1][0] = fmaf(a1, b4.x, acc[1][0]); acc[1][1] = fmaf(a1, b4.y, acc[1][1]);
            acc[1][2] = fmaf(a1, b4.z, acc[1][2]); acc[1][3] = fmaf(a1, b4.w, acc[1][3]);
            acc[2][0] = fmaf(a2, b4.x, acc[2][0]); acc[2][1] = fmaf(a2, b4.y, acc[2][1]);
            acc[2][2] = fmaf(a2, b4.z, acc[2][2]); acc[2][3] = fmaf(a2, b4.w, acc[2][3]);
            acc[3][0] = fmaf(a3, b4.x, acc[3][0]); acc[3][1] = fmaf(a3, b4.y, acc[3][1]);
            acc[3][2] = fmaf(a3, b4.z, acc[3][2]); acc[3][3] = fmaf(a3, b4.w, acc[3][3]);
        }
        __syncthreads();
    }

    #pragma unroll
    for (int i = 0; i < 4; i++) {
        const int r = row0 + ty * 4 + i;
        #pragma unroll
        for (int j = 0; j < 4; j++) {
            const int c = col0 + tx * 4 + j;
            if (c < N) {
                float v = acc[i][j] + bias[c];
                if (RELU_OUT) v = fmaxf(v, 0.f);
                C[(size_t)r * N + c] = v;
            }
        }
    }
}

// ===========================================================================
// GRU scan kernel: 16 clusters x 8 CTAs, 128 threads/CTA.
//   cluster cl  -> batch rows cl*4 .. cl*4+3
//   CTA rank cr -> hidden units u = cr*32 .. cr*32+31 (all 3 gates)
// SMEM per CTA:
//   w_s   [96][260] floats  (rows 0-31: r-gate, 32-63: z, 64-95: n; +4 pad)
//   h_s   [2][4][256]       double-buffered hidden (whole cluster's 4 rows)
//   part  [3][4][4][32]     partial dot sums (gate, b, kchunk, j)
//   dn_s  [4][2048] int     dones
//   c_s   [4] int           last-done index per row
// One barrier.cluster per step; h broadcast via mapa + st.shared::cluster.
// ===========================================================================
#define W_OFF   0
#define H_OFF   24960                 // 96*260
#define P_OFF   27008                 // H_OFF + 2048
#define D_OFF   28544                 // P_OFF + 1536
#define C_OFF   36736                 // D_OFF + 8192
#define SMEM_FLOATS 36744
#define SMEM_BYTES  (SMEM_FLOATS * 4)

__device__ __forceinline__ void dsmem_bcast_f32(uint32_t laddr, float v)
{
    #pragma unroll
    for (int p = 0; p < 8; p++) {
        uint32_t ra;
        asm volatile("mapa.shared::cluster.u32 %0, %1, %2;"
                     : "=r"(ra) : "r"(laddr), "r"(p));
        asm volatile("st.shared::cluster.f32 [%0], %1;"
                     :: "r"(ra), "f"(v) : "memory");
    }
}

__device__ __forceinline__ void cluster_bar()
{
    asm volatile("barrier.cluster.arrive.aligned;" ::: "memory");
    asm volatile("barrier.cluster.wait.aligned;"   ::: "memory");
}

__global__ void __cluster_dims__(8, 1, 1) __launch_bounds__(128, 1)
gru_scan_kernel(const float* __restrict__ gi,   const float* __restrict__ w_hh,
                const float* __restrict__ b_ih, const float* __restrict__ b_hh,
                const int*   __restrict__ dones, const float* __restrict__ h0,
                float* __restrict__ gru_out, float* __restrict__ hx_out)
{
    extern __shared__ float sm[];
    float* w_s  = sm + W_OFF;
    float* h_s  = sm + H_OFF;
    float* part = sm + P_OFF;
    int*   dn_s = (int*)(sm + D_OFF);
    int*   c_s  = (int*)(sm + C_OFF);

    const int tid = threadIdx.x;
    const int q   = tid >> 5;      // k-chunk in dot phase; batch row in epilogue
    const int j   = tid & 31;      // unit lane
    const int b   = q;             // epilogue role
    uint32_t cr;
    asm("mov.u32 %0, %%cluster_ctarank;" : "=r"(cr));
    const int cl = blockIdx.x >> 3;
    const int u0 = (int)cr * 32;
    const int u  = u0 + j;
    const int bg = cl * 4 + b;

    if (tid < 4) c_s[tid] = 0;
    __syncthreads();

    // ---- stage w_hh slice (rows u, 256+u, 512+u for u in slice) ----
    for (int idx = tid; idx < 96 * 64; idx += 128) {
        int r  = idx >> 6, k4 = idx & 63;
        int gr = (r < 32) ? (u0 + r) : ((r < 64) ? (256 + u0 + r - 32)
                                                 : (512 + u0 + r - 64));
        *(float4*)(w_s + r * 260 + k4 * 4) =
            *(const float4*)(w_hh + (size_t)gr * 256 + k4 * 4);
    }
    // ---- h0 for this cluster's 4 rows ----
    for (int idx = tid; idx < 1024; idx += 128)
        h_s[idx] = h0[(size_t)cl * 1024 + idx];
    // ---- dones + last-done index ----
    for (int idx = tid; idx < 8192; idx += 128) {
        int d = dones[(size_t)cl * 8192 + idx];
        dn_s[idx] = d;
        if (d) atomicMax(&c_s[idx >> 11], idx & 2047);
    }
    // biases (epilogue role)
    const float bhr = b_hh[u], bhz = b_hh[256 + u], bhn = b_hh[512 + u];
    const float bir = b_ih[u], biz = b_ih[256 + u], bin_ = b_ih[512 + u];
    __syncthreads();
    const int cb   = c_s[b];
    const int maxc = max(max(c_s[0], c_s[1]), max(c_s[2], c_s[3]));
    cluster_bar();   // all CTAs staged before any DSMEM traffic

    // dot-phase pointers: thread (q, j) handles k-chunk [q*64, q*64+64)
    const float* wr_p = w_s + (j)      * 260 + q * 64;
    const float* wz_p = w_s + (32 + j) * 260 + q * 64;
    const float* wn_p = w_s + (64 + j) * 260 + q * 64;

    const uint32_t h_s_u32 = (uint32_t)__cvta_generic_to_shared(h_s);
    const uint32_t my_off0 = (uint32_t)((b * 256 + u) * 4);
    const uint32_t my_off1 = my_off0 + 4096;

    int s = 0;

    #define DOT_PHASE()                                                        \
        float accr[4] = {0.f,0.f,0.f,0.f};                                     \
        float accz[4] = {0.f,0.f,0.f,0.f};                                     \
        float accn[4] = {0.f,0.f,0.f,0.f};                                     \
        {                                                                      \
            const float* hp = h_s + s * 1024 + q * 64;                         \
            _Pragma("unroll 4")                                                \
            for (int kk = 0; kk < 16; kk++) {                                  \
                float4 wr4 = *(const float4*)(wr_p + kk * 4);                  \
                float4 wz4 = *(const float4*)(wz_p + kk * 4);                  \
                float4 wn4 = *(const float4*)(wn_p + kk * 4);                  \
                _Pragma("unroll")                                              \
                for (int bb = 0; bb < 4; bb++) {                               \
                    float4 h4 = *(const float4*)(hp + bb * 256 + kk * 4);      \
                    accr[bb] = fmaf(wr4.x, h4.x, accr[bb]);                    \
                    accr[bb] = fmaf(wr4.y, h4.y, accr[bb]);                    \
                    accr[bb] = fmaf(wr4.z, h4.z, accr[bb]);                    \
                    accr[bb] = fmaf(wr4.w, h4.w, accr[bb]);                    \
                    accz[bb] = fmaf(wz4.x, h4.x, accz[bb]);                    \
                    accz[bb] = fmaf(wz4.y, h4.y, accz[bb]);                    \
                    accz[bb] = fmaf(wz4.z, h4.z, accz[bb]);                    \
                    accz[bb] = fmaf(wz4.w, h4.w, accz[bb]);                    \
                    accn[bb] = fmaf(wn4.x, h4.x, accn[bb]);                    \
                    accn[bb] = fmaf(wn4.y, h4.y, accn[bb]);                    \
                    accn[bb] = fmaf(wn4.z, h4.z, accn[bb]);                    \
                    accn[bb] = fmaf(wn4.w, h4.w, accn[bb]);                    \
                }                                                              \
            }                                                                  \
            _Pragma("unroll")                                                  \
            for (int bb = 0; bb < 4; bb++) {                                   \
                part[(0 * 4 + bb) * 128 + q * 32 + j] = accr[bb];              \
                part[(1 * 4 + bb) * 128 + q * 32 + j] = accz[bb];              \
                part[(2 * 4 + bb) * 128 + q * 32 + j] = accn[bb];              \
            }                                                                  \
        }                                                                      \
        __syncthreads();                                                       \
        float sr = 0.f, sz = 0.f, sn = 0.f;                                    \
        _Pragma("unroll")                                                      \
        for (int qq = 0; qq < 4; qq++) {                                       \
            sr += part[(0 * 4 + b) * 128 + qq * 32 + j];                       \
            sz += part[(1 * 4 + b) * 128 + qq * 32 + j];                       \
            sn += part[(2 * 4 + b) * 128 + qq * 32 + j];                       \
        }

    // ------------------- main scan: 2048 steps -------------------
    for (int t = 0; t < LQ; t++) {
        // prefetch gi for the epilogue (hidden under the dot)
        const size_t gbase = ((size_t)bg * LQ + t) * G3;
        const float gir = gi[gbase + u];
        const float giz = gi[gbase + 256 + u];
        const float gin = gi[gbase + 512 + u];
        const int   d   = dn_s[b * 2048 + t];

        DOT_PHASE();

        const float m    = d ? 0.f : 1.f;
        const float hold = h_s[s * 1024 + b * 256 + u] * m;
        const float rr = 1.f / (1.f + expf(-(gir + m * sr + bhr)));
        const float zz = 1.f / (1.f + expf(-(giz + m * sz + bhz)));
        const float nn = tanhf(gin + rr * (m * sn + bhn));
        const float hnew = (1.f - zz) * nn + zz * hold;

        gru_out[(size_t)bg * (LQ * 256) + (size_t)t * 256 + u] = hnew;
        dsmem_bcast_f32(h_s_u32 + (s ? my_off0 : my_off1), hnew);
        cluster_bar();
        s ^= 1;
    }

    // ------------------- tail: zero-input steps, masked by k < c[b] -------
    for (int k = 0; k < maxc; k++) {
        DOT_PHASE();

        const float hold = h_s[s * 1024 + b * 256 + u];
        const float rr = 1.f / (1.f + expf(-(bir + sr + bhr)));
        const float zz = 1.f / (1.f + expf(-(biz + sz + bhz)));
        const float nn = tanhf(bin_ + rr * (sn + bhn));
        const float hnew = (1.f - zz) * nn + zz * hold;
        const float hnx  = (k < cb) ? hnew : hold;

        dsmem_bcast_f32(h_s_u32 + (s ? my_off0 : my_off1), hnx);
        cluster_bar();
        s ^= 1;
    }

    hx_out[(size_t)bg * 256 + u] = h_s[s * 1024 + b * 256 + u];
    #undef DOT_PHASE
}

// ===========================================================================
// Launch
// ===========================================================================
extern "C" void kernel_launch(void* const* d_in, const int* in_sizes, int n_in,
                              void* d_out, int out_size)
{
    const float* state = (const float*)d_in[0];
    const float* h0    = (const float*)d_in[1];
    const int*   dones = (const int*)  d_in[2];
    const float* w_ih  = (const float*)d_in[3];
    const float* w_hh  = (const float*)d_in[4];
    const float* b_ih  = (const float*)d_in[5];
    const float* b_hh  = (const float*)d_in[6];
    const float* fc0_w = (const float*)d_in[7];
    const float* fc0_b = (const float*)d_in[8];
    const float* fc1_w = (const float*)d_in[9];
    const float* fc1_b = (const float*)d_in[10];
    const float* fc2_w = (const float*)d_in[11];
    const float* fc2_b = (const float*)d_in[12];

    float* out = (float*)d_out;
    float* q_out  = out;
    float* gru    = out + Q_ELEMS;
    float* hx     = out + Q_ELEMS + GRU_ELEMS;

    float *gi, *m0, *m1;
    cudaGetSymbolAddress((void**)&gi, g_gi);
    cudaGetSymbolAddress((void**)&m0, g_m0);
    cudaGetSymbolAddress((void**)&m1, g_m1);

    cudaFuncSetAttribute(gru_scan_kernel,
                         cudaFuncAttributeMaxDynamicSharedMemorySize, SMEM_BYTES);

    const dim3 blk(256);

    // gi = state @ w_ih^T + b_ih   [131072, 768]
    gemm_bias<false, false><<<dim3(ROWS_TOT / BM, G3 / BN), blk>>>(
        state, w_ih, b_ih, gi, ROWS_TOT, G3, INQ);

    // sequential GRU scan (writes gru_out + next_hx)
    gru_scan_kernel<<<128, 128, SMEM_BYTES>>>(
        gi, w_hh, b_ih, b_hh, dones, h0, gru, hx);

    // MLP head
    gemm_bias<true,  true ><<<dim3(ROWS_TOT / BM, HH / BN), blk>>>(
        gru, fc0_w, fc0_b, m0, ROWS_TOT, HH, HH);
    gemm_bias<false, true ><<<dim3(ROWS_TOT / BM, HH / BN), blk>>>(
        m0, fc1_w, fc1_b, m1, ROWS_TOT, HH, HH);
    gemm_bias<false, false><<<dim3(ROWS_TOT / BM, 1), blk>>>(
        m1, fc2_w, fc2_b, q_out, ROWS_TOT, AQ, HH);
}

// round 16
// speedup vs baseline: 1.6462x; 1.6462x over previous
#include <cuda_runtime.h>
#include <cstdint>
#include <cstddef>

// Problem dims
#define NB   64
#define LQ   2048
#define INQ  128
#define HH   256
#define AQ   18
#define G3   768
#define ROWS_TOT 131072              // NB*LQ

// Output layout (floats): q [64,2048,18] | gru_out [64,2048,256] | next_hx [1,64,256]
#define Q_ELEMS    2359296ULL
#define GRU_ELEMS  33554432ULL

// ---------------------------------------------------------------------------
// Scratch (static device globals -- allocation APIs are forbidden)
// ---------------------------------------------------------------------------
__device__ float g_gi[(size_t)ROWS_TOT * G3];   // input projections [N*L, 768]
__device__ float g_m0[(size_t)ROWS_TOT * HH];   // fc0 output
__device__ float g_m1[(size_t)ROWS_TOT * HH];   // fc1 output

// ===========================================================================
// Generic tiled fp32 GEMM:  C[M,N] = act( A[M,K] @ B[N,K]^T + bias[N] )
// (unchanged from R14 -- known good; scan is the bottleneck)
// ===========================================================================
#define BM 64
#define BN 64
#define BKK 16

template<bool RELU_IN, bool RELU_OUT>
__global__ void __launch_bounds__(256)
gemm_bias(const float* __restrict__ A, const float* __restrict__ B,
          const float* __restrict__ bias, float* __restrict__ C,
          int M, int N, int K)
{
    __shared__ float As[BM * BKK];
    __shared__ float Bs[BKK * BN];

    const int tid  = threadIdx.x;
    const int row0 = blockIdx.x * BM;
    const int col0 = blockIdx.y * BN;
    const int lr = tid >> 2;
    const int lc = tid & 3;
    const int ty = tid >> 4;
    const int tx = tid & 15;

    float acc[4][4];
    #pragma unroll
    for (int i = 0; i < 4; i++)
        #pragma unroll
        for (int j = 0; j < 4; j++) acc[i][j] = 0.f;

    for (int k0 = 0; k0 < K; k0 += BKK) {
        float4 av = *(const float4*)(A + (size_t)(row0 + lr) * K + k0 + lc * 4);
        if (RELU_IN) {
            av.x = fmaxf(av.x, 0.f); av.y = fmaxf(av.y, 0.f);
            av.z = fmaxf(av.z, 0.f); av.w = fmaxf(av.w, 0.f);
        }
        *(float4*)(As + lr * BKK + lc * 4) = av;

        float4 bv = make_float4(0.f, 0.f, 0.f, 0.f);
        if (col0 + lr < N)
            bv = *(const float4*)(B + (size_t)(col0 + lr) * K + k0 + lc * 4);
        Bs[(lc * 4 + 0) * BN + lr] = bv.x;
        Bs[(lc * 4 + 1) * BN + lr] = bv.y;
        Bs[(lc * 4 + 2) * BN + lr] = bv.z;
        Bs[(lc * 4 + 3) * BN + lr] = bv.w;
        __syncthreads();

        #pragma unroll
        for (int k = 0; k < BKK; k++) {
            float a0 = As[(ty * 4 + 0) * BKK + k];
            float a1 = As[(ty * 4 + 1) * BKK + k];
            float a2 = As[(ty * 4 + 2) * BKK + k];
            float a3 = As[(ty * 4 + 3) * BKK + k];
            float4 b4 = *(const float4*)(Bs + k * BN + tx * 4);
            acc[0][0] = fmaf(a0, b4.x, acc[0][0]); acc[0][1] = fmaf(a0, b4.y, acc[0][1]);
            acc[0][2] = fmaf(a0, b4.z, acc[0][2]); acc[0][3] = fmaf(a0, b4.w, acc[0][3]);
            acc[1][0] = fmaf(a1, b4.x, acc[1][0]); acc[1][1] = fmaf(a1, b4.y, acc[1][1]);
            acc[1][2] = fmaf(a1, b4.z, acc[1][2]); acc[1][3] = fmaf(a1, b4.w, acc[1][3]);
            acc[2][0] = fmaf(a2, b4.x, acc[2][0]); acc[2][1] = fmaf(a2, b4.y, acc[2][1]);
            acc[2][2] = fmaf(a2, b4.z, acc[2][2]); acc[2][3] = fmaf(a2, b4.w, acc[2][3]);
            acc[3][0] = fmaf(a3, b4.x, acc[3][0]); acc[3][1] = fmaf(a3, b4.y, acc[3][1]);
            acc[3][2] = fmaf(a3, b4.z, acc[3][2]); acc[3][3] = fmaf(a3, b4.w, acc[3][3]);
        }
        __syncthreads();
    }

    #pragma unroll
    for (int i = 0; i < 4; i++) {
        const int r = row0 + ty * 4 + i;
        #pragma unroll
        for (int j = 0; j < 4; j++) {
            const int c = col0 + tx * 4 + j;
            if (c < N) {
                float v = acc[i][j] + bias[c];
                if (RELU_OUT) v = fmaxf(v, 0.f);
                C[(size_t)r * N + c] = v;
            }
        }
    }
}

// ===========================================================================
// PTX helpers for the scan
// ===========================================================================
typedef unsigned long long ull;

__device__ __forceinline__ ull pk2(float a, float b) {
    ull r; asm("mov.b64 %0, {%1, %2};" : "=l"(r) : "f"(a), "f"(b)); return r;
}
__device__ __forceinline__ float2 upk2(ull v) {
    float2 f; asm("mov.b64 {%0, %1}, %2;" : "=f"(f.x), "=f"(f.y) : "l"(v)); return f;
}
__device__ __forceinline__ void fma2(ull& acc, ull a, ull b) {
    asm("fma.rn.f32x2 %0, %1, %2, %0;" : "+l"(acc) : "l"(a), "l"(b));
}
__device__ __forceinline__ void lds_v2u64(ull& a, ull& b, unsigned int addr) {
    asm volatile("ld.shared.v2.b64 {%0, %1}, [%2];"
                 : "=l"(a), "=l"(b) : "r"(addr));
}
__device__ __forceinline__ unsigned int mapa_u32(unsigned int laddr, unsigned int rank) {
    unsigned int r;
    asm("mapa.shared::cluster.u32 %0, %1, %2;" : "=r"(r) : "r"(laddr), "r"(rank));
    return r;
}
__device__ __forceinline__ void st_cluster_v4(unsigned int raddr, float4 v) {
    asm volatile("st.shared::cluster.v4.f32 [%0], {%1, %2, %3, %4};"
                 :: "r"(raddr), "f"(v.x), "f"(v.y), "f"(v.z), "f"(v.w) : "memory");
}
__device__ __forceinline__ void cluster_bar() {
    asm volatile("barrier.cluster.arrive.aligned;" ::: "memory");
    asm volatile("barrier.cluster.wait.aligned;"   ::: "memory");
}
// Saturating fast sigmoid/tanh (no inf/inf NaN at extreme preactivations).
__device__ __forceinline__ float sig_fast(float x) {
    return __fdividef(1.f, 1.f + __expf(-x));
}
__device__ __forceinline__ float tanh_fast(float x) {
    // 1 - 2/(e^{2x}+1): x->+inf => 1; x->-inf => -1; overflow-safe.
    return 1.f - __fdividef(2.f, __expf(2.f * x) + 1.f);
}

// ===========================================================================
// GRU scan v2.1: 16 clusters x 8 CTAs x 256 threads. w_hh in REGISTERS.
//   cluster cl  -> batch rows cl*4 .. cl*4+3
//   CTA rank cr -> hidden units u = cr*32 .. cr*32+31 (all 3 gates)
//   warp wid (0..7) -> k-chunk [wid*32, wid*32+32); lane -> unit
//   Each thread holds w[3 gates][32 k] = 48 f32x2 pairs in registers.
//   Dot phase: h loads lane-invariant (broadcast, conflict-free);
//   192 fma.rn.f32x2 per thread per step. 8-way cross-warp reduce in SMEM.
//   h broadcast to all 8 peer CTAs via st.shared::cluster.v4.f32; one
//   barrier.cluster per step.
// SMEM (floats): h_s[2][4][256] @0 | part[12][256] @2048 | hstage[128] @5120
//                c_s[4] @5248 | dn_s[4][2048] @5252
// ===========================================================================
#define SC_H_OFF    0
#define SC_P_OFF    2048
#define SC_HS_OFF   5120
#define SC_C_OFF    5248
#define SC_D_OFF    5252
#define SC_SMEM_FLOATS 13444
#define SC_SMEM_BYTES  (SC_SMEM_FLOATS * 4)

__global__ void __cluster_dims__(8, 1, 1) __launch_bounds__(256, 1)
gru_scan_kernel(const float* __restrict__ gi,   const float* __restrict__ w_hh,
                const float* __restrict__ b_ih, const float* __restrict__ b_hh,
                const int*   __restrict__ dones, const float* __restrict__ h0,
                float* __restrict__ gru_out, float* __restrict__ hx_out)
{
    extern __shared__ float sm[];
    float* h_s    = sm + SC_H_OFF;
    float* part   = sm + SC_P_OFF;
    float* hstage = sm + SC_HS_OFF;
    int*   c_s    = (int*)(sm + SC_C_OFF);
    int*   dn_s   = (int*)(sm + SC_D_OFF);

    const int tid  = threadIdx.x;
    const int wid  = tid >> 5;
    const int lane = tid & 31;
    unsigned int cr;
    asm("mov.u32 %0, %%cluster_ctarank;" : "=r"(cr));
    const int cl = blockIdx.x >> 3;
    const int u0 = (int)cr * 32;
    const int u  = u0 + lane;          // this thread's unit (dot + epilogue)

    if (tid < 4) c_s[tid] = 0;
    __syncthreads();

    // ---- stage h0 (full cluster copy per CTA) + dones ----
    for (int idx = tid; idx < 1024; idx += 256)
        h_s[idx] = h0[(size_t)cl * 1024 + idx];
    for (int idx = tid; idx < 8192; idx += 256) {
        int d = dones[(size_t)cl * 8192 + idx];
        dn_s[idx] = d;
        if (d) atomicMax(&c_s[idx >> 11], idx & 2047);
    }

    // ---- w_hh slice -> registers (48 f32x2 pairs) ----
    ull w2[48];
    #pragma unroll
    for (int g = 0; g < 3; g++) {
        const float4* rp = (const float4*)(w_hh + (size_t)(g * 256 + u) * 256 + wid * 32);
        #pragma unroll
        for (int j = 0; j < 8; j++) {
            float4 f = rp[j];
            w2[g * 16 + j * 2 + 0] = pk2(f.x, f.y);
            w2[g * 16 + j * 2 + 1] = pk2(f.z, f.w);
        }
    }

    // biases for epilogue role
    const float bhr = b_hh[u], bhz = b_hh[256 + u], bhn = b_hh[512 + u];
    const float bir = b_ih[u], biz = b_ih[256 + u], bin_ = b_ih[512 + u];
    __syncthreads();

    const int eb   = tid >> 5;                         // epilogue batch row (tid<128)
    const int cb   = (tid < 128) ? c_s[eb] : 0;
    const int maxc = max(max(c_s[0], c_s[1]), max(c_s[2], c_s[3]));
    cluster_bar();                                     // staging done cluster-wide

    const unsigned int smbase = (unsigned int)__cvta_generic_to_shared(sm);
    unsigned int peer[8];
    #pragma unroll
    for (int p = 0; p < 8; p++) peer[p] = mapa_u32(smbase, p);

    const int sp = tid >> 5;           // send role: peer index (warp -> one peer)
    const int sc = tid & 31;           // send role: float4 chunk (32 chunks = 128 floats)
    // dst float index: b*256 + u0 + (sc&7)*4   [BUGFIX: batch stride 256, not 1024]
    const unsigned int send_off = ((unsigned)((sc >> 3) * 256 + u0 + (sc & 7) * 4)) * 4u;

    int s = 0;

    #define SC_DOT()                                                           \
        ull acc[12];                                                           \
        _Pragma("unroll")                                                      \
        for (int i = 0; i < 12; i++) acc[i] = 0ULL;                            \
        {                                                                      \
            const unsigned int hb = smbase + s * 4096 + wid * 128;             \
            _Pragma("unroll")                                                  \
            for (int bb = 0; bb < 4; bb++) {                                   \
                ull h2[16];                                                    \
                _Pragma("unroll")                                              \
                for (int j = 0; j < 8; j++)                                    \
                    lds_v2u64(h2[2*j], h2[2*j+1], hb + bb * 1024 + j * 16);    \
                _Pragma("unroll")                                              \
                for (int g = 0; g < 3; g++)                                    \
                    _Pragma("unroll")                                          \
                    for (int i = 0; i < 16; i++)                               \
                        fma2(acc[g * 4 + bb], w2[g * 16 + i], h2[i]);          \
            }                                                                  \
        }                                                                      \
        _Pragma("unroll")                                                      \
        for (int i = 0; i < 12; i++) {                                         \
            float2 f = upk2(acc[i]);                                           \
            part[i * 256 + tid] = f.x + f.y;                                   \
        }                                                                      \
        __syncthreads();                                                       \
        float sr = 0.f, sz = 0.f, sn = 0.f;                                    \
        if (tid < 128) {                                                       \
            _Pragma("unroll")                                                  \
            for (int q = 0; q < 8; q++) {                                      \
                sr += part[(0 + eb) * 256 + q * 32 + lane];                    \
                sz += part[(4 + eb) * 256 + q * 32 + lane];                    \
                sn += part[(8 + eb) * 256 + q * 32 + lane];                    \
            }                                                                  \
        }

    #define SC_SEND()                                                          \
        __syncthreads();                                                       \
        {                                                                      \
            float4 v = ((const float4*)hstage)[sc];                            \
            st_cluster_v4(peer[sp] + (s ^ 1) * 4096 + send_off, v);            \
        }                                                                      \
        cluster_bar();                                                         \
        s ^= 1;

    // ------------------- main scan: 2048 steps -------------------
    for (int t = 0; t < LQ; t++) {
        float gir = 0.f, giz = 0.f, gin = 0.f;
        int d = 0;
        if (tid < 128) {
            const size_t gb = ((size_t)(cl * 4 + eb) * LQ + t) * G3;
            gir = gi[gb + u];
            giz = gi[gb + 256 + u];
            gin = gi[gb + 512 + u];
            d = dn_s[eb * 2048 + t];
        }

        SC_DOT();

        if (tid < 128) {
            const float m    = d ? 0.f : 1.f;
            const float hold = h_s[s * 1024 + eb * 256 + u] * m;
            const float r  = sig_fast(gir + m * sr + bhr);
            const float z  = sig_fast(giz + m * sz + bhz);
            const float nn = tanh_fast(gin + r * (m * sn + bhn));
            const float hnew = (1.f - z) * nn + z * hold;
            gru_out[(size_t)(cl * 4 + eb) * (LQ * 256) + (size_t)t * 256 + u] = hnew;
            hstage[tid] = hnew;
        }

        SC_SEND();
    }

    // ------------------- tail: zero-input steps, masked by k < c[b] -------
    for (int k = 0; k < maxc; k++) {
        SC_DOT();

        if (tid < 128) {
            const float hold = h_s[s * 1024 + eb * 256 + u];
            const float r  = sig_fast(bir + sr + bhr);
            const float z  = sig_fast(biz + sz + bhz);
            const float nn = tanh_fast(bin_ + r * (sn + bhn));
            const float hnew = (1.f - z) * nn + z * hold;
            hstage[tid] = (k < cb) ? hnew : hold;
        }

        SC_SEND();
    }

    if (tid < 128)
        hx_out[(size_t)(cl * 4 + eb) * 256 + u] = h_s[s * 1024 + eb * 256 + u];

    #undef SC_DOT
    #undef SC_SEND
}

// ===========================================================================
// Launch
// ===========================================================================
extern "C" void kernel_launch(void* const* d_in, const int* in_sizes, int n_in,
                              void* d_out, int out_size)
{
    const float* state = (const float*)d_in[0];
    const float* h0    = (const float*)d_in[1];
    const int*   dones = (const int*)  d_in[2];
    const float* w_ih  = (const float*)d_in[3];
    const float* w_hh  = (const float*)d_in[4];
    const float* b_ih  = (const float*)d_in[5];
    const float* b_hh  = (const float*)d_in[6];
    const float* fc0_w = (const float*)d_in[7];
    const float* fc0_b = (const float*)d_in[8];
    const float* fc1_w = (const float*)d_in[9];
    const float* fc1_b = (const float*)d_in[10];
    const float* fc2_w = (const float*)d_in[11];
    const float* fc2_b = (const float*)d_in[12];

    float* out   = (float*)d_out;
    float* q_out = out;
    float* gru   = out + Q_ELEMS;
    float* hx    = out + Q_ELEMS + GRU_ELEMS;

    float *gi, *m0, *m1;
    cudaGetSymbolAddress((void**)&gi, g_gi);
    cudaGetSymbolAddress((void**)&m0, g_m0);
    cudaGetSymbolAddress((void**)&m1, g_m1);

    cudaFuncSetAttribute(gru_scan_kernel,
                         cudaFuncAttributeMaxDynamicSharedMemorySize, SC_SMEM_BYTES);

    const dim3 blk(256);

    // gi = state @ w_ih^T + b_ih   [131072, 768]
    gemm_bias<false, false><<<dim3(ROWS_TOT / BM, G3 / BN), blk>>>(
        state, w_ih, b_ih, gi, ROWS_TOT, G3, INQ);

    // sequential GRU scan (writes gru_out + next_hx)
    gru_scan_kernel<<<128, 256, SC_SMEM_BYTES>>>(
        gi, w_hh, b_ih, b_hh, dones, h0, gru, hx);

    // MLP head
    gemm_bias<true,  true ><<<dim3(ROWS_TOT / BM, HH / BN), blk>>>(
        gru, fc0_w, fc0_b, m0, ROWS_TOT, HH, HH);
    gemm_bias<false, true ><<<dim3(ROWS_TOT / BM, HH / BN), blk>>>(
        m0, fc1_w, fc1_b, m1, ROWS_TOT, HH, HH);
    gemm_bias<false, false><<<dim3(ROWS_TOT / BM, 1), blk>>>(
        m1, fc2_w, fc2_b, q_out, ROWS_TOT, AQ, HH);
}

// round 17
// speedup vs baseline: 1.7233x; 1.0469x over previous
#include <cuda_runtime.h>
#include <cstdint>
#include <cstddef>

// Problem dims
#define NB   64
#define LQ   2048
#define INQ  128
#define HH   256
#define AQ   18
#define G3   768
#define ROWS_TOT 131072              // NB*LQ

// Output layout (floats): q [64,2048,18] | gru_out [64,2048,256] | next_hx [1,64,256]
#define Q_ELEMS    2359296ULL
#define GRU_ELEMS  33554432ULL

// ---------------------------------------------------------------------------
// Scratch (static device globals -- allocation APIs are forbidden)
// ---------------------------------------------------------------------------
__device__ float g_gi[(size_t)ROWS_TOT * G3];   // input projections [N*L, 768]
__device__ float g_m0[(size_t)ROWS_TOT * HH];   // fc0 output
__device__ float g_m1[(size_t)ROWS_TOT * HH];   // fc1 output

// ===========================================================================
// Generic tiled fp32 GEMM:  C[M,N] = act( A[M,K] @ B[N,K]^T + bias[N] )
// (unchanged -- known good; scan is the bottleneck)
// ===========================================================================
#define BM 64
#define BN 64
#define BKK 16

template<bool RELU_IN, bool RELU_OUT>
__global__ void __launch_bounds__(256)
gemm_bias(const float* __restrict__ A, const float* __restrict__ B,
          const float* __restrict__ bias, float* __restrict__ C,
          int M, int N, int K)
{
    __shared__ float As[BM * BKK];
    __shared__ float Bs[BKK * BN];

    const int tid  = threadIdx.x;
    const int row0 = blockIdx.x * BM;
    const int col0 = blockIdx.y * BN;
    const int lr = tid >> 2;
    const int lc = tid & 3;
    const int ty = tid >> 4;
    const int tx = tid & 15;

    float acc[4][4];
    #pragma unroll
    for (int i = 0; i < 4; i++)
        #pragma unroll
        for (int j = 0; j < 4; j++) acc[i][j] = 0.f;

    for (int k0 = 0; k0 < K; k0 += BKK) {
        float4 av = *(const float4*)(A + (size_t)(row0 + lr) * K + k0 + lc * 4);
        if (RELU_IN) {
            av.x = fmaxf(av.x, 0.f); av.y = fmaxf(av.y, 0.f);
            av.z = fmaxf(av.z, 0.f); av.w = fmaxf(av.w, 0.f);
        }
        *(float4*)(As + lr * BKK + lc * 4) = av;

        float4 bv = make_float4(0.f, 0.f, 0.f, 0.f);
        if (col0 + lr < N)
            bv = *(const float4*)(B + (size_t)(col0 + lr) * K + k0 + lc * 4);
        Bs[(lc * 4 + 0) * BN + lr] = bv.x;
        Bs[(lc * 4 + 1) * BN + lr] = bv.y;
        Bs[(lc * 4 + 2) * BN + lr] = bv.z;
        Bs[(lc * 4 + 3) * BN + lr] = bv.w;
        __syncthreads();

        #pragma unroll
        for (int k = 0; k < BKK; k++) {
            float a0 = As[(ty * 4 + 0) * BKK + k];
            float a1 = As[(ty * 4 + 1) * BKK + k];
            float a2 = As[(ty * 4 + 2) * BKK + k];
            float a3 = As[(ty * 4 + 3) * BKK + k];
            float4 b4 = *(const float4*)(Bs + k * BN + tx * 4);
            acc[0][0] = fmaf(a0, b4.x, acc[0][0]); acc[0][1] = fmaf(a0, b4.y, acc[0][1]);
            acc[0][2] = fmaf(a0, b4.z, acc[0][2]); acc[0][3] = fmaf(a0, b4.w, acc[0][3]);
            acc[1][0] = fmaf(a1, b4.x, acc[1][0]); acc[1][1] = fmaf(a1, b4.y, acc[1][1]);
            acc[1][2] = fmaf(a1, b4.z, acc[1][2]); acc[1][3] = fmaf(a1, b4.w, acc[1][3]);
            acc[2][0] = fmaf(a2, b4.x, acc[2][0]); acc[2][1] = fmaf(a2, b4.y, acc[2][1]);
            acc[2][2] = fmaf(a2, b4.z, acc[2][2]); acc[2][3] = fmaf(a2, b4.w, acc[2][3]);
            acc[3][0] = fmaf(a3, b4.x, acc[3][0]); acc[3][1] = fmaf(a3, b4.y, acc[3][1]);
            acc[3][2] = fmaf(a3, b4.z, acc[3][2]); acc[3][3] = fmaf(a3, b4.w, acc[3][3]);
        }
        __syncthreads();
    }

    #pragma unroll
    for (int i = 0; i < 4; i++) {
        const int r = row0 + ty * 4 + i;
        #pragma unroll
        for (int j = 0; j < 4; j++) {
            const int c = col0 + tx * 4 + j;
            if (c < N) {
                float v = acc[i][j] + bias[c];
                if (RELU_OUT) v = fmaxf(v, 0.f);
                C[(size_t)r * N + c] = v;
            }
        }
    }
}

// Dummy no-op kernel: shifts launch order so ncu's fixed capture slot lands
// on the scan kernel (diagnostic for the next round).
__global__ void dummy_k() {}

// ===========================================================================
// PTX helpers for the scan
// ===========================================================================
typedef unsigned long long ull;

__device__ __forceinline__ ull pk2(float a, float b) {
    ull r; asm("mov.b64 %0, {%1, %2};" : "=l"(r) : "f"(a), "f"(b)); return r;
}
__device__ __forceinline__ float2 upk2(ull v) {
    float2 f; asm("mov.b64 {%0, %1}, %2;" : "=f"(f.x), "=f"(f.y) : "l"(v)); return f;
}
__device__ __forceinline__ void fma2(ull& acc, ull a, ull b) {
    asm("fma.rn.f32x2 %0, %1, %2, %0;" : "+l"(acc) : "l"(a), "l"(b));
}
__device__ __forceinline__ void lds_v2u64(ull& a, ull& b, unsigned int addr) {
    asm volatile("ld.shared.v2.b64 {%0, %1}, [%2];"
                 : "=l"(a), "=l"(b) : "r"(addr));
}
__device__ __forceinline__ unsigned int mapa_u32(unsigned int laddr, unsigned int rank) {
    unsigned int r;
    asm("mapa.shared::cluster.u32 %0, %1, %2;" : "=r"(r) : "r"(laddr), "r"(rank));
    return r;
}
__device__ __forceinline__ void st_async_b64(unsigned int raddr, ull v, unsigned int rmbar) {
    asm volatile("st.async.shared::cluster.mbarrier::complete_tx::bytes.b64 [%0], %1, [%2];"
                 :: "r"(raddr), "l"(v), "r"(rmbar) : "memory");
}
__device__ __forceinline__ void mbar_init(unsigned int mbar, unsigned int count) {
    asm volatile("mbarrier.init.shared.b64 [%0], %1;"
                 :: "r"(mbar), "r"(count) : "memory");
}
__device__ __forceinline__ void mbar_expect_tx(unsigned int mbar, unsigned int bytes) {
    asm volatile("mbarrier.arrive.expect_tx.shared.b64 _, [%0], %1;"
                 :: "r"(mbar), "r"(bytes) : "memory");
}
__device__ __forceinline__ void mbar_wait(unsigned int mbar, unsigned int parity) {
    unsigned int done;
    asm volatile(
        "{\n\t.reg .pred p;\n\t"
        "mbarrier.try_wait.parity.acquire.cta.shared::cta.b64 p, [%1], %2;\n\t"
        "selp.b32 %0, 1, 0, p;\n\t}"
        : "=r"(done) : "r"(mbar), "r"(parity) : "memory");
    if (!done) {
        asm volatile(
            "{\n\t.reg .pred P1;\n\t"
            "WAIT_LOOP_%=:\n\t"
            "mbarrier.try_wait.parity.acquire.cta.shared::cta.b64 P1, [%0], %1, 0x989680;\n\t"
            "@P1 bra.uni WAIT_DONE_%=;\n\t"
            "bra.uni WAIT_LOOP_%=;\n\t"
            "WAIT_DONE_%=:\n\t}"
            :: "r"(mbar), "r"(parity) : "memory");
    }
}
__device__ __forceinline__ void cluster_bar() {
    asm volatile("barrier.cluster.arrive.aligned;" ::: "memory");
    asm volatile("barrier.cluster.wait.aligned;"   ::: "memory");
}
__device__ __forceinline__ float sig_fast(float x) {
    return __fdividef(1.f, 1.f + __expf(-x));
}
__device__ __forceinline__ float tanh_fast(float x) {
    return 1.f - __fdividef(2.f, __expf(2.f * x) + 1.f);   // overflow-safe
}

// ===========================================================================
// GRU scan v3: mbarrier/st.async sync (no per-step cluster barrier).
//   16 clusters x 8 CTAs x 256 threads; w_hh in registers (48 f32x2/thread).
//   Per step: dot (192 fma2/thread) -> 3x STS.128 partials -> reduce ->
//   epilogue -> st.async h broadcast with complete_tx -> mbarrier parity wait.
// SMEM (floats): h_s[2][4][256] @0 | part4[3][256] float4 @2048 |
//                hstage[128] @5120 | c_s[4] @5248 | mb[2] @5252 |
//                dn_s[4][2048] @5256
// ===========================================================================
#define SC_H_OFF    0
#define SC_P_OFF    2048
#define SC_HS_OFF   5120
#define SC_C_OFF    5248
#define SC_MB_OFF   5252              // byte offset 21008, 16B aligned
#define SC_D_OFF    5256
#define SC_SMEM_FLOATS 13448
#define SC_SMEM_BYTES  (SC_SMEM_FLOATS * 4)
#define SC_MB_BYTE  (SC_MB_OFF * 4)
#define SC_TX_BYTES 4096u             // 8 CTAs x 32 lanes x 2 x 8B

__global__ void __cluster_dims__(8, 1, 1) __launch_bounds__(256, 1)
gru_scan_kernel(const float* __restrict__ gi,   const float* __restrict__ w_hh,
                const float* __restrict__ b_ih, const float* __restrict__ b_hh,
                const int*   __restrict__ dones, const float* __restrict__ h0,
                float* __restrict__ gru_out, float* __restrict__ hx_out)
{
    extern __shared__ float sm[];
    float* h_s    = sm + SC_H_OFF;
    float* hstage = sm + SC_HS_OFF;
    int*   c_s    = (int*)(sm + SC_C_OFF);
    int*   dn_s   = (int*)(sm + SC_D_OFF);

    const int tid  = threadIdx.x;
    const int wid  = tid >> 5;
    const int lane = tid & 31;
    unsigned int cr;
    asm("mov.u32 %0, %%cluster_ctarank;" : "=r"(cr));
    const int cl = blockIdx.x >> 3;
    const int u0 = (int)cr * 32;
    const int u  = u0 + lane;          // this thread's unit (dot + epilogue)

    const unsigned int smbase = (unsigned int)__cvta_generic_to_shared(sm);
    const unsigned int mb_l   = smbase + SC_MB_BYTE;

    if (tid < 4) c_s[tid] = 0;
    if (tid == 0) { mbar_init(mb_l, 1); mbar_init(mb_l + 8, 1); }
    __syncthreads();

    // ---- stage h0 (full cluster copy per CTA) + dones ----
    for (int idx = tid; idx < 1024; idx += 256)
        h_s[idx] = h0[(size_t)cl * 1024 + idx];
    for (int idx = tid; idx < 8192; idx += 256) {
        int d = dones[(size_t)cl * 8192 + idx];
        dn_s[idx] = d;
        if (d) atomicMax(&c_s[idx >> 11], idx & 2047);
    }

    // ---- w_hh slice -> registers (48 f32x2 pairs) ----
    ull w2[48];
    #pragma unroll
    for (int g = 0; g < 3; g++) {
        const float4* rp = (const float4*)(w_hh + (size_t)(g * 256 + u) * 256 + wid * 32);
        #pragma unroll
        for (int j = 0; j < 8; j++) {
            float4 f = rp[j];
            w2[g * 16 + j * 2 + 0] = pk2(f.x, f.y);
            w2[g * 16 + j * 2 + 1] = pk2(f.z, f.w);
        }
    }

    const float bhr = b_hh[u], bhz = b_hh[256 + u], bhn = b_hh[512 + u];
    const float bir = b_ih[u], biz = b_ih[256 + u], bin_ = b_ih[512 + u];
    __syncthreads();

    const int eb   = tid >> 5;                         // epilogue batch row (tid<128)
    const int cb   = (tid < 128) ? c_s[eb] : 0;
    const int maxc = max(max(c_s[0], c_s[1]), max(c_s[2], c_s[3]));

    // arm both mbarriers for their first phase, then cluster-wide sync so all
    // CTAs' mbarriers/buffers are staged before any st.async traffic.
    if (tid == 0) { mbar_expect_tx(mb_l, SC_TX_BYTES); mbar_expect_tx(mb_l + 8, SC_TX_BYTES); }
    cluster_bar();

    unsigned int peer_h[8], peer_mb[8];
    #pragma unroll
    for (int p = 0; p < 8; p++) {
        peer_h[p]  = mapa_u32(smbase, p);
        peer_mb[p] = peer_h[p] + SC_MB_BYTE;
    }

    const int sp = wid;                // send role: peer index
    const int sc = lane;               // send role: float4 chunk of hstage
    const unsigned int send_off = ((unsigned)((sc >> 3) * 256 + u0 + (sc & 7) * 4)) * 4u;

    int s = 0;
    int phb = 0;                       // parity bits for mb[0], mb[1]

    // gi prefetch for t=0
    float cgr = 0.f, cgz = 0.f, cgn = 0.f;
    if (tid < 128) {
        const size_t gb = ((size_t)(cl * 4 + eb) * LQ + 0) * G3;
        cgr = gi[gb + u]; cgz = gi[gb + 256 + u]; cgn = gi[gb + 512 + u];
    }

    #define SC_DOT()                                                           \
        ull acc[12];                                                           \
        _Pragma("unroll")                                                      \
        for (int i = 0; i < 12; i++) acc[i] = 0ULL;                            \
        {                                                                      \
            const unsigned int hb = smbase + s * 4096 + wid * 128;             \
            _Pragma("unroll")                                                  \
            for (int bb = 0; bb < 4; bb++) {                                   \
                ull h2[16];                                                    \
                _Pragma("unroll")                                              \
                for (int j = 0; j < 8; j++)                                    \
                    lds_v2u64(h2[2*j], h2[2*j+1], hb + bb * 1024 + j * 16);    \
                _Pragma("unroll")                                              \
                for (int g = 0; g < 3; g++)                                    \
                    _Pragma("unroll")                                          \
                    for (int i = 0; i < 16; i++)                               \
                        fma2(acc[g * 4 + bb], w2[g * 16 + i], h2[i]);          \
            }                                                                  \
        }                                                                      \
        {   /* pack 4 bb-sums per gate -> 3x STS.128 (drain-cheap) */          \
            float4* p4 = (float4*)(sm + SC_P_OFF);                             \
            _Pragma("unroll")                                                  \
            for (int g = 0; g < 3; g++) {                                      \
                float2 f0 = upk2(acc[g*4+0]), f1 = upk2(acc[g*4+1]);           \
                float2 f2 = upk2(acc[g*4+2]), f3 = upk2(acc[g*4+3]);           \
                p4[g * 256 + tid] = make_float4(f0.x+f0.y, f1.x+f1.y,          \
                                                f2.x+f2.y, f3.x+f3.y);         \
            }                                                                  \
        }                                                                      \
        __syncthreads();                                                       \
        float sr = 0.f, sz = 0.f, sn = 0.f;                                    \
        if (tid < 128) {                                                       \
            const float* pp = sm + SC_P_OFF;                                   \
            _Pragma("unroll")                                                  \
            for (int q = 0; q < 8; q++) {                                      \
                const int base = q * 32 + lane;                                \
                sr += pp[(0 * 256 + base) * 4 + eb];                           \
                sz += pp[(1 * 256 + base) * 4 + eb];                           \
                sn += pp[(2 * 256 + base) * 4 + eb];                           \
            }                                                                  \
        }

    #define SC_SEND_WAIT()                                                     \
        __syncthreads();                                                       \
        {                                                                      \
            const float4 v = ((const float4*)hstage)[sc];                      \
            const unsigned int db = peer_h[sp] + (s ^ 1) * 4096 + send_off;    \
            const unsigned int mb = peer_mb[sp] + (s ^ 1) * 8;                 \
            st_async_b64(db,     pk2(v.x, v.y), mb);                           \
            st_async_b64(db + 8, pk2(v.z, v.w), mb);                           \
        }                                                                      \
        {                                                                      \
            const int nb = s ^ 1;                                              \
            mbar_wait(mb_l + nb * 8, (phb >> nb) & 1);                         \
            phb ^= (1 << nb);                                                  \
            if (tid == 0) mbar_expect_tx(mb_l + nb * 8, SC_TX_BYTES);          \
        }                                                                      \
        s ^= 1;

    // ------------------- main scan: 2048 steps -------------------
    for (int t = 0; t < LQ; t++) {
        // prefetch gi for step t+1 (a full step of latency cover)
        float ngr = 0.f, ngz = 0.f, ngn = 0.f;
        if (tid < 128) {
            const int tt = (t + 1 < LQ) ? t + 1 : LQ - 1;
            const size_t gb = ((size_t)(cl * 4 + eb) * LQ + tt) * G3;
            ngr = gi[gb + u]; ngz = gi[gb + 256 + u]; ngn = gi[gb + 512 + u];
        }

        SC_DOT();

        if (tid < 128) {
            const int   d    = dn_s[eb * 2048 + t];
            const float m    = d ? 0.f : 1.f;
            const float hold = h_s[s * 1024 + eb * 256 + u] * m;
            const float r  = sig_fast(cgr + m * sr + bhr);
            const float z  = sig_fast(cgz + m * sz + bhz);
            const float nn = tanh_fast(cgn + r * (m * sn + bhn));
            const float hnew = (1.f - z) * nn + z * hold;
            gru_out[(size_t)(cl * 4 + eb) * (LQ * 256) + (size_t)t * 256 + u] = hnew;
            hstage[tid] = hnew;
        }

        SC_SEND_WAIT();

        cgr = ngr; cgz = ngz; cgn = ngn;
    }

    // ------------------- tail: zero-input steps, masked by k < c[b] -------
    for (int k = 0; k < maxc; k++) {
        SC_DOT();

        if (tid < 128) {
            const float hold = h_s[s * 1024 + eb * 256 + u];
            const float r  = sig_fast(bir + sr + bhr);
            const float z  = sig_fast(biz + sz + bhz);
            const float nn = tanh_fast(bin_ + r * (sn + bhn));
            const float hnew = (1.f - z) * nn + z * hold;
            hstage[tid] = (k < cb) ? hnew : hold;
        }

        SC_SEND_WAIT();
    }

    if (tid < 128)
        hx_out[(size_t)(cl * 4 + eb) * 256 + u] = h_s[s * 1024 + eb * 256 + u];

    cluster_bar();   // no CTA exits while peers' st.async may be in flight

    #undef SC_DOT
    #undef SC_SEND_WAIT
}

// ===========================================================================
// Launch
// ===========================================================================
extern "C" void kernel_launch(void* const* d_in, const int* in_sizes, int n_in,
                              void* d_out, int out_size)
{
    const float* state = (const float*)d_in[0];
    const float* h0    = (const float*)d_in[1];
    const int*   dones = (const int*)  d_in[2];
    const float* w_ih  = (const float*)d_in[3];
    const float* w_hh  = (const float*)d_in[4];
    const float* b_ih  = (const float*)d_in[5];
    const float* b_hh  = (const float*)d_in[6];
    const float* fc0_w = (const float*)d_in[7];
    const float* fc0_b = (const float*)d_in[8];
    const float* fc1_w = (const float*)d_in[9];
    const float* fc1_b = (const float*)d_in[10];
    const float* fc2_w = (const float*)d_in[11];
    const float* fc2_b = (const float*)d_in[12];

    float* out   = (float*)d_out;
    float* q_out = out;
    float* gru   = out + Q_ELEMS;
    float* hx    = out + Q_ELEMS + GRU_ELEMS;

    float *gi, *m0, *m1;
    cudaGetSymbolAddress((void**)&gi, g_gi);
    cudaGetSymbolAddress((void**)&m0, g_m0);
    cudaGetSymbolAddress((void**)&m1, g_m1);

    cudaFuncSetAttribute(gru_scan_kernel,
                         cudaFuncAttributeMaxDynamicSharedMemorySize, SC_SMEM_BYTES);

    const dim3 blk(256);

    // gi = state @ w_ih^T + b_ih   [131072, 768]
    gemm_bias<false, false><<<dim3(ROWS_TOT / BM, G3 / BN), blk>>>(
        state, w_ih, b_ih, gi, ROWS_TOT, G3, INQ);

    // launch-slot shims so ncu's fixed capture slot profiles the scan
    dummy_k<<<1, 32>>>();
    dummy_k<<<1, 32>>>();

    // sequential GRU scan (writes gru_out + next_hx)
    gru_scan_kernel<<<128, 256, SC_SMEM_BYTES>>>(
        gi, w_hh, b_ih, b_hh, dones, h0, gru, hx);

    // MLP head
    gemm_bias<true,  true ><<<dim3(ROWS_TOT / BM, HH / BN), blk>>>(
        gru, fc0_w, fc0_b, m0, ROWS_TOT, HH, HH);
    gemm_bias<false, true ><<<dim3(ROWS_TOT / BM, HH / BN), blk>>>(
        m0, fc1_w, fc1_b, m1, ROWS_TOT, HH, HH);
    gemm_bias<false, false><<<dim3(ROWS_TOT / BM, 1), blk>>>(
        m1, fc2_w, fc2_b, q_out, ROWS_TOT, AQ, HH);
}